// round 15
// baseline (speedup 1.0000x reference)
#include <cuda_runtime.h>
#include <cstdint>

// Problem constants
#define B_   4
#define S_   2048
#define EMB_ 1024
#define H_   16
#define DH_  64
#define M_   (B_ * S_)          // 8192 rows

// Scratch (module-static device memory; no cudaMalloc anywhere)
__device__ float g_Q[B_ * H_ * S_ * DH_];   // [bh][s][d]  tf32-rounded, pre-scaled 1/8
__device__ float g_K[B_ * H_ * S_ * DH_];   // tf32-rounded
__device__ float g_V[B_ * H_ * S_ * DH_];   // tf32-rounded
__device__ float g_ctx[M_ * EMB_];          // [b*s][emb] tf32-rounded
__device__ float g_xr[M_ * EMB_];           // tf32-rounded x
__device__ float g_Wt[4 * EMB_ * EMB_];     // tf32-rounded TRANSPOSED W: [z][n][k]

// ---------------------------------------------------------------------------
// Helpers
// ---------------------------------------------------------------------------
__device__ __forceinline__ uint32_t tf32r(float f) {
    uint32_t u;
    asm("cvt.rna.tf32.f32 %0, %1;" : "=r"(u) : "f"(f));
    return u;
}

__device__ __forceinline__ void mma_tf32(float* c, const uint32_t* a,
                                         uint32_t b0, uint32_t b1) {
    asm volatile(
        "mma.sync.aligned.m16n8k8.row.col.f32.tf32.tf32.f32 "
        "{%0,%1,%2,%3}, {%4,%5,%6,%7}, {%8,%9}, {%0,%1,%2,%3};"
        : "+f"(c[0]), "+f"(c[1]), "+f"(c[2]), "+f"(c[3])
        : "r"(a[0]), "r"(a[1]), "r"(a[2]), "r"(a[3]), "r"(b0), "r"(b1));
}

// ---------------------------------------------------------------------------
// Prep 1: round x to tf32.  grid 8192 x 256 (float4 granularity).
// ---------------------------------------------------------------------------
__global__ __launch_bounds__(256) void round_x_kernel(const float* __restrict__ x)
{
    size_t i = (size_t)blockIdx.x * 256 + threadIdx.x;
    float4 v = ((const float4*)x)[i];
    uint4 u;
    u.x = tf32r(v.x); u.y = tf32r(v.y); u.z = tf32r(v.z); u.w = tf32r(v.w);
    ((uint4*)g_xr)[i] = u;
}

// ---------------------------------------------------------------------------
// Prep 2: transpose + round weights.  g_Wt[z][n][k] = round(W[z][k][n])
// 32x32 tiles, 256 threads (32x8).  grid (32, 32, 4).
// ---------------------------------------------------------------------------
__global__ __launch_bounds__(256) void transpose_w_kernel(
    const float* __restrict__ W0, const float* __restrict__ W1,
    const float* __restrict__ W2, const float* __restrict__ W3)
{
    __shared__ uint32_t t[32][33];
    const int z = blockIdx.z;
    const float* W = (z == 0) ? W0 : (z == 1) ? W1 : (z == 2) ? W2 : W3;
    float* out = g_Wt + (size_t)z * EMB_ * EMB_;
    const int x0 = blockIdx.x * 32, y0 = blockIdx.y * 32;   // x0: n, y0: k
    const int tx = threadIdx.x & 31, ty = threadIdx.x >> 5;
#pragma unroll
    for (int i = 0; i < 4; i++)
        t[ty + i * 8][tx] = tf32r(W[(size_t)(y0 + ty + i * 8) * EMB_ + x0 + tx]);
    __syncthreads();
#pragma unroll
    for (int i = 0; i < 4; i++)
        ((uint32_t*)out)[(size_t)(x0 + ty + i * 8) * EMB_ + y0 + tx] = t[tx][ty + i * 8];
}

// ---------------------------------------------------------------------------
// tf32 mma.sync GEMM v3: 4 warps, warp tile 64x64, CTA tile 128x128, BK=32.
// Fragment smem traffic 64KB/CTA/chunk (was 96KB with 8 warps).
// A (= [m][k]) and Bt (= [n][k], pre-transposed) both stored pair-interleaved
// in k per 8-chunk, row stride 40 u32 -> conflict-free LDS.64 fragments.
// out[m,n] = sum_k A[m,k] * Bt[n,k] + bias[n]
// mode: 0 = row-major fp32 out (oproj), 1 = scatter+round (K/V),
//       2 = scatter+*0.125+round (Q)
// ---------------------------------------------------------------------------
__device__ __forceinline__ void gemm_mma_body(
    const float* __restrict__ A, const float* __restrict__ Bt,
    const float* __restrict__ bias, float* __restrict__ out, int mode)
{
    __shared__ uint32_t As[128][40];   // [m][k pair-interleaved]
    __shared__ uint32_t Bs[128][40];   // [n][k pair-interleaved]

    const int tid  = threadIdx.x;      // 0..127
    const int lane = tid & 31;
    const int wid  = tid >> 5;         // 0..3
    const int wm   = wid & 1;
    const int wn   = wid >> 1;
    const int m0   = blockIdx.y * 128;
    const int n0   = blockIdx.x * 128;
    const int gm   = wm * 64;
    const int gn   = wn * 64;
    const int row4 = lane >> 2;
    const int kq   = lane & 3;

    float acc[4][8][4];
#pragma unroll
    for (int mt = 0; mt < 4; mt++)
#pragma unroll
        for (int nt = 0; nt < 8; nt++)
#pragma unroll
            for (int i = 0; i < 4; i++) acc[mt][nt][i] = 0.f;

    // loader: 512 seg-slots each for A and B (128 rows x 4 segs of 8 k)
    size_t aoff[4], boff[4];
    uint32_t* sA[4];
    uint32_t* sB[4];
#pragma unroll
    for (int i = 0; i < 4; i++) {
        int v   = tid + 128 * i;       // 0..511
        int row = v >> 2;              // 0..127
        int seg = v & 3;               // 0..3
        aoff[i] = (size_t)(m0 + row) * EMB_ + seg * 8;
        boff[i] = (size_t)(n0 + row) * EMB_ + seg * 8;
        sA[i] = &As[row][seg * 8];
        sB[i] = &Bs[row][seg * 8];
    }

    uint4 pa[4][2], pb[4][2];
#pragma unroll
    for (int i = 0; i < 4; i++) {
        pa[i][0] = *(const uint4*)(A + aoff[i]);
        pa[i][1] = *(const uint4*)(A + aoff[i] + 4);
        pb[i][0] = *(const uint4*)(Bt + boff[i]);
        pb[i][1] = *(const uint4*)(Bt + boff[i] + 4);
    }

#pragma unroll 1
    for (int c = 0; c < 32; c++) {
        if (c > 0) __syncthreads();
#pragma unroll
        for (int i = 0; i < 4; i++) {
            uint4 a = pa[i][0], b = pa[i][1];
            uint4 u0, u1;
            u0.x = a.x; u0.y = b.x; u0.z = a.y; u0.w = b.y;
            u1.x = a.z; u1.y = b.z; u1.z = a.w; u1.w = b.w;
            *(uint4*)sA[i] = u0;
            *(uint4*)(sA[i] + 4) = u1;
            a = pb[i][0]; b = pb[i][1];
            u0.x = a.x; u0.y = b.x; u0.z = a.y; u0.w = b.y;
            u1.x = a.z; u1.y = b.z; u1.z = a.w; u1.w = b.w;
            *(uint4*)sB[i] = u0;
            *(uint4*)(sB[i] + 4) = u1;
        }
        __syncthreads();

        if (c < 31) {
            size_t ka = (size_t)(c + 1) * 32;
#pragma unroll
            for (int i = 0; i < 4; i++) {
                pa[i][0] = *(const uint4*)(A + aoff[i] + ka);
                pa[i][1] = *(const uint4*)(A + aoff[i] + ka + 4);
                pb[i][0] = *(const uint4*)(Bt + boff[i] + ka);
                pb[i][1] = *(const uint4*)(Bt + boff[i] + ka + 4);
            }
        }

#pragma unroll
        for (int s = 0; s < 4; s++) {
            const int sc = s * 8 + 2 * kq;
            uint32_t a[4][4];
#pragma unroll
            for (int mt = 0; mt < 4; mt++) {
                uint2 qa = *(uint2*)&As[gm + mt * 16 + row4][sc];
                uint2 qb = *(uint2*)&As[gm + mt * 16 + row4 + 8][sc];
                a[mt][0] = qa.x; a[mt][1] = qb.x;
                a[mt][2] = qa.y; a[mt][3] = qb.y;
            }
#pragma unroll
            for (int nt = 0; nt < 8; nt++) {
                uint2 kb = *(uint2*)&Bs[gn + nt * 8 + row4][sc];
#pragma unroll
                for (int mt = 0; mt < 4; mt++)
                    mma_tf32(acc[mt][nt], a[mt], kb.x, kb.y);
            }
        }
    }

    // epilogue
#pragma unroll
    for (int mt = 0; mt < 4; mt++) {
        int r0 = m0 + gm + mt * 16 + row4;
#pragma unroll
        for (int nt = 0; nt < 8; nt++) {
            int cc = n0 + gn + nt * 8 + 2 * kq;
            float s0 = acc[mt][nt][0] + bias[cc];
            float s1 = acc[mt][nt][1] + bias[cc + 1];
            float s2 = acc[mt][nt][2] + bias[cc];
            float s3 = acc[mt][nt][3] + bias[cc + 1];
            if (mode) {
                if (mode == 2) { s0 *= 0.125f; s1 *= 0.125f; s2 *= 0.125f; s3 *= 0.125f; }
                float2 v0, v1;
                v0.x = __uint_as_float(tf32r(s0));
                v0.y = __uint_as_float(tf32r(s1));
                v1.x = __uint_as_float(tf32r(s2));
                v1.y = __uint_as_float(tf32r(s3));
                int h = cc >> 6, d = cc & 63;
                int b0r = r0 >> 11, sq0 = r0 & 2047;
                int b1r = (r0 + 8) >> 11, sq1 = (r0 + 8) & 2047;
                *(float2*)(out + ((size_t)(b0r * H_ + h) * S_ + sq0) * DH_ + d) = v0;
                *(float2*)(out + ((size_t)(b1r * H_ + h) * S_ + sq1) * DH_ + d) = v1;
            } else {
                float2 v0, v1;
                v0.x = s0; v0.y = s1;
                v1.x = s2; v1.y = s3;
                *(float2*)(out + (size_t)r0 * EMB_ + cc) = v0;
                *(float2*)(out + (size_t)(r0 + 8) * EMB_ + cc) = v1;
            }
        }
    }
}

__global__ __launch_bounds__(128, 2) void qkv_mma_kernel(
    const float* __restrict__ bq, const float* __restrict__ bk,
    const float* __restrict__ bv)
{
    const int z = blockIdx.z;
    const float* Bt   = g_Wt + (size_t)z * (EMB_ * EMB_);
    const float* bias = (z == 0) ? bq : (z == 1) ? bk : bv;
    float* out        = (z == 0) ? g_Q : (z == 1) ? g_K : g_V;
    gemm_mma_body(g_xr, Bt, bias, out, (z == 0) ? 2 : 1);
}

__global__ __launch_bounds__(128, 2) void oproj_mma_kernel(
    const float* __restrict__ bo, float* __restrict__ out)
{
    gemm_mma_body(g_ctx, g_Wt + (size_t)3 * (EMB_ * EMB_), bo, out, 0);
}

// ---------------------------------------------------------------------------
// Flash attention v4 (unchanged from R13): register-resident P via shuffles,
// 64-query CTA, 2 CTAs/SM.
// ---------------------------------------------------------------------------
#define O_QS  0
#define O_KS  4608
#define O_VS  13824
#define O_RED 23040
#define O_LB  23168
#define ATTN_SMEM_U32 23232
#define ATTN_SMEM_BYTES (ATTN_SMEM_U32 * 4)

__global__ __launch_bounds__(256, 2) void attn_mma_kernel()
{
    extern __shared__ uint32_t sm[];
    float* smf = (float*)sm;

    const int tid  = threadIdx.x;
    const int lane = tid & 31;
    const int wid  = tid >> 5;
    const int wm   = wid & 3;
    const int wn   = wid >> 2;
    const int row4 = lane >> 2;
    const int kq   = lane & 3;
    const int gm   = wm * 16;
    const int gn   = wn * 64;

    const int bh = blockIdx.y;
    const int q0 = blockIdx.x * 64;

    const float* Qg = g_Q + ((size_t)bh * S_ + q0) * DH_;
    const float* Kg = g_K + (size_t)bh * S_ * DH_;
    const float* Vg = g_V + (size_t)bh * S_ * DH_;

    const int src1 = (lane & ~3) | (kq >> 1);
    const int src2 = src1 + 2;
    const bool oddq = (kq & 1);

#pragma unroll
    for (int i = 0; i < 2; i++) {
        int v   = tid + 256 * i;
        int row = v >> 3;
        int seg = v & 7;
        const uint4* p = (const uint4*)(Qg + row * DH_ + seg * 8);
        uint4 a = p[0], b = p[1];
        uint4 u0, u1;
        u0.x = a.x; u0.y = b.x; u0.z = a.y; u0.w = b.y;
        u1.x = a.z; u1.y = b.z; u1.z = a.w; u1.w = b.w;
        *(uint4*)&sm[O_QS + row * 72 + seg * 8]     = u0;
        *(uint4*)&sm[O_QS + row * 72 + seg * 8 + 4] = u1;
    }

    float Oa[8][4];
#pragma unroll
    for (int nt = 0; nt < 8; nt++)
#pragma unroll
        for (int i = 0; i < 4; i++) Oa[nt][i] = 0.f;
    float m_run[2] = {-1e30f, -1e30f};
    float l_run[2] = {0.f, 0.f};

#pragma unroll 1
    for (int kt = 0; kt < S_ / 128; kt++) {
        __syncthreads();
        const int k0 = kt * 128;
#pragma unroll
        for (int i = 0; i < 4; i++) {
            int v   = tid + 256 * i;
            int row = v >> 3;
            int seg = v & 7;
            const uint4* p = (const uint4*)(Kg + (size_t)(k0 + row) * DH_ + seg * 8);
            uint4 a = p[0], b = p[1];
            uint4 u0, u1;
            u0.x = a.x; u0.y = b.x; u0.z = a.y; u0.w = b.y;
            u1.x = a.z; u1.y = b.z; u1.z = a.w; u1.w = b.w;
            *(uint4*)&sm[O_KS + row * 72 + seg * 8]     = u0;
            *(uint4*)&sm[O_KS + row * 72 + seg * 8 + 4] = u1;
        }
#pragma unroll
        for (int i = 0; i < 8; i++) {
            int v   = tid + 256 * i;
            int row = v >> 4;
            int c4  = v & 15;
            uint4 uv = *(const uint4*)(Vg + (size_t)(k0 + row) * DH_ + c4 * 4);
            *(uint4*)&sm[O_VS + row * 72 + c4 * 4] = uv;
        }
        __syncthreads();

        float acc[8][4];
#pragma unroll
        for (int nt = 0; nt < 8; nt++)
#pragma unroll
            for (int i = 0; i < 4; i++) acc[nt][i] = 0.f;

#pragma unroll
        for (int s = 0; s < 8; s++) {
            const int sc = s * 8 + 2 * kq;
            uint2 qa = *(uint2*)&sm[O_QS + (gm + row4) * 72 + sc];
            uint2 qb = *(uint2*)&sm[O_QS + (gm + row4 + 8) * 72 + sc];
            uint32_t a[4];
            a[0] = qa.x; a[1] = qb.x; a[2] = qa.y; a[3] = qb.y;
#pragma unroll
            for (int nt = 0; nt < 8; nt++) {
                uint2 kb = *(uint2*)&sm[O_KS + (gn + nt * 8 + row4) * 72 + sc];
                mma_tf32(acc[nt], a, kb.x, kb.y);
            }
        }

        float rmax[2];
        rmax[0] = acc[0][0];
        rmax[1] = acc[0][2];
#pragma unroll
        for (int nt = 0; nt < 8; nt++) {
            rmax[0] = fmaxf(rmax[0], fmaxf(acc[nt][0], acc[nt][1]));
            rmax[1] = fmaxf(rmax[1], fmaxf(acc[nt][2], acc[nt][3]));
        }
#pragma unroll
        for (int h = 0; h < 2; h++) {
            rmax[h] = fmaxf(rmax[h], __shfl_xor_sync(0xffffffffu, rmax[h], 1));
            rmax[h] = fmaxf(rmax[h], __shfl_xor_sync(0xffffffffu, rmax[h], 2));
        }
        if (kq == 0) {
            smf[O_RED + wn * 64 + gm + row4]     = rmax[0];
            smf[O_RED + wn * 64 + gm + 8 + row4] = rmax[1];
        }
        __syncthreads();

        float scale[2];
#pragma unroll
        for (int h = 0; h < 2; h++) {
            int r = gm + h * 8 + row4;
            float mtile = fmaxf(smf[O_RED + r], smf[O_RED + 64 + r]);
            float mnew  = fmaxf(m_run[h], mtile);
            scale[h] = __expf(m_run[h] - mnew);
            m_run[h] = mnew;
        }

#pragma unroll
        for (int nt = 0; nt < 8; nt++) {
            acc[nt][0] = __expf(acc[nt][0] - m_run[0]);
            acc[nt][1] = __expf(acc[nt][1] - m_run[0]);
            acc[nt][2] = __expf(acc[nt][2] - m_run[1]);
            acc[nt][3] = __expf(acc[nt][3] - m_run[1]);
        }
        float rsum[2] = {0.f, 0.f};
#pragma unroll
        for (int nt = 0; nt < 8; nt++) {
            rsum[0] += acc[nt][0] + acc[nt][1];
            rsum[1] += acc[nt][2] + acc[nt][3];
        }
#pragma unroll
        for (int h = 0; h < 2; h++) {
            rsum[h] += __shfl_xor_sync(0xffffffffu, rsum[h], 1);
            rsum[h] += __shfl_xor_sync(0xffffffffu, rsum[h], 2);
            l_run[h] = l_run[h] * scale[h] + rsum[h];
        }
#pragma unroll
        for (int nt = 0; nt < 8; nt++) {
            acc[nt][0] = __uint_as_float(tf32r(acc[nt][0]));
            acc[nt][1] = __uint_as_float(tf32r(acc[nt][1]));
            acc[nt][2] = __uint_as_float(tf32r(acc[nt][2]));
            acc[nt][3] = __uint_as_float(tf32r(acc[nt][3]));
        }

#pragma unroll
        for (int nt = 0; nt < 8; nt++) {
            Oa[nt][0] *= scale[0];
            Oa[nt][1] *= scale[0];
            Oa[nt][2] *= scale[1];
            Oa[nt][3] *= scale[1];
        }

#pragma unroll
        for (int ink = 0; ink < 8; ink++) {
            float s1p0 = __shfl_sync(0xffffffffu, acc[ink][0], src1);
            float s1p1 = __shfl_sync(0xffffffffu, acc[ink][1], src1);
            float s1p2 = __shfl_sync(0xffffffffu, acc[ink][2], src1);
            float s1p3 = __shfl_sync(0xffffffffu, acc[ink][3], src1);
            float s2p0 = __shfl_sync(0xffffffffu, acc[ink][0], src2);
            float s2p1 = __shfl_sync(0xffffffffu, acc[ink][1], src2);
            float s2p2 = __shfl_sync(0xffffffffu, acc[ink][2], src2);
            float s2p3 = __shfl_sync(0xffffffffu, acc[ink][3], src2);
            uint32_t a[4];
            a[0] = __float_as_uint(oddq ? s1p1 : s1p0);
            a[1] = __float_as_uint(oddq ? s1p3 : s1p2);
            a[2] = __float_as_uint(oddq ? s2p1 : s2p0);
            a[3] = __float_as_uint(oddq ? s2p3 : s2p2);
            const int kr0 = (gn + ink * 8 + kq) * 72;
            const int kr1 = (gn + ink * 8 + kq + 4) * 72;
#pragma unroll
            for (int nt = 0; nt < 8; nt++) {
                uint32_t b0 = sm[O_VS + kr0 + nt * 8 + row4];
                uint32_t b1 = sm[O_VS + kr1 + nt * 8 + row4];
                mma_tf32(Oa[nt], a, b0, b1);
            }
        }
    }

    __syncthreads();
    if (wn == 1) {
#pragma unroll
        for (int nt = 0; nt < 8; nt++) {
            int d = nt * 8 + 2 * kq;
            float2 v0, v1;
            v0.x = Oa[nt][0]; v0.y = Oa[nt][1];
            v1.x = Oa[nt][2]; v1.y = Oa[nt][3];
            *(float2*)&smf[O_KS + (gm + row4) * 72 + d]     = v0;
            *(float2*)&smf[O_KS + (gm + 8 + row4) * 72 + d] = v1;
        }
        if (kq == 0) {
            smf[O_LB + gm + row4]     = l_run[0];
            smf[O_LB + gm + 8 + row4] = l_run[1];
        }
    }
    __syncthreads();
    if (wn == 0) {
        const int b = bh >> 4;
        const int h = bh & 15;
        int r0 = gm + row4;
        int r1 = gm + 8 + row4;
        float inv0 = 1.f / (l_run[0] + smf[O_LB + r0]);
        float inv1 = 1.f / (l_run[1] + smf[O_LB + r1]);
        float* o0 = g_ctx + ((size_t)(b * S_) + q0 + r0) * EMB_ + h * DH_;
        float* o1 = g_ctx + ((size_t)(b * S_) + q0 + r1) * EMB_ + h * DH_;
#pragma unroll
        for (int nt = 0; nt < 8; nt++) {
            int d = nt * 8 + 2 * kq;
            float2 p0 = *(float2*)&smf[O_KS + r0 * 72 + d];
            float2 p1 = *(float2*)&smf[O_KS + r1 * 72 + d];
            float2 v0, v1;
            v0.x = __uint_as_float(tf32r((Oa[nt][0] + p0.x) * inv0));
            v0.y = __uint_as_float(tf32r((Oa[nt][1] + p0.y) * inv0));
            v1.x = __uint_as_float(tf32r((Oa[nt][2] + p1.x) * inv1));
            v1.y = __uint_as_float(tf32r((Oa[nt][3] + p1.y) * inv1));
            *(float2*)(o0 + d) = v0;
            *(float2*)(o1 + d) = v1;
        }
    }
}

// ---------------------------------------------------------------------------
// Launch
// ---------------------------------------------------------------------------
extern "C" void kernel_launch(void* const* d_in, const int* in_sizes, int n_in,
                              void* d_out, int out_size)
{
    const float* x  = (const float*)d_in[0];
    const float* Wq = (const float*)d_in[1];
    const float* bq = (const float*)d_in[2];
    const float* Wk = (const float*)d_in[3];
    const float* bk = (const float*)d_in[4];
    const float* Wv = (const float*)d_in[5];
    const float* bv = (const float*)d_in[6];
    const float* Wo = (const float*)d_in[7];
    const float* bo = (const float*)d_in[8];
    float* out = (float*)d_out;

    cudaFuncSetAttribute(attn_mma_kernel,
                         cudaFuncAttributeMaxDynamicSharedMemorySize, ATTN_SMEM_BYTES);

    round_x_kernel<<<8192, 256>>>(x);                     // x: 2M float4

    dim3 gT(EMB_ / 32, EMB_ / 32, 4);                     // (32, 32, 4)
    transpose_w_kernel<<<gT, 256>>>(Wq, Wk, Wv, Wo);

    dim3 gQKV(EMB_ / 128, M_ / 128, 3);                   // (8, 64, 3)
    qkv_mma_kernel<<<gQKV, 128>>>(bq, bk, bv);

    dim3 gAttn(S_ / 64, B_ * H_);                         // (32, 64)
    attn_mma_kernel<<<gAttn, 256, ATTN_SMEM_BYTES>>>();

    dim3 gO(EMB_ / 128, M_ / 128);                        // (8, 64)
    oproj_mma_kernel<<<gO, 128>>>(bo, out);
}

// round 17
// speedup vs baseline: 1.7963x; 1.7963x over previous
#include <cuda_runtime.h>
#include <cuda_fp16.h>
#include <cstdint>

// Problem constants
#define B_   4
#define S_   2048
#define EMB_ 1024
#define H_   16
#define DH_  64
#define M_   (B_ * S_)          // 8192 rows

// Scratch (module-static device memory; no cudaMalloc anywhere)
__device__ __half g_Qh[B_ * H_ * S_ * DH_];   // [bh][s][d]  fp16, pre-scaled 1/8
__device__ __half g_Kh[B_ * H_ * S_ * DH_];   // [bh][s][d]  fp16
__device__ __half g_Vth[B_ * H_ * DH_ * S_];  // TRANSPOSED [bh][d][s] fp16
__device__ __half g_ctxh[M_ * EMB_];          // [b*s][emb] fp16
__device__ __half g_xh[M_ * EMB_];            // fp16 x
__device__ __half g_Wth[4 * EMB_ * EMB_];     // fp16 TRANSPOSED W: [z][n][k]

// ---------------------------------------------------------------------------
// Helpers
// ---------------------------------------------------------------------------
__device__ __forceinline__ uint32_t f2h2(float lo, float hi) {
    __half2 h = __floats2half2_rn(lo, hi);
    return *(uint32_t*)&h;
}

__device__ __forceinline__ void mma_f16(float* c, const uint32_t* a,
                                        uint32_t b0, uint32_t b1) {
    asm volatile(
        "mma.sync.aligned.m16n8k16.row.col.f32.f16.f16.f32 "
        "{%0,%1,%2,%3}, {%4,%5,%6,%7}, {%8,%9}, {%0,%1,%2,%3};"
        : "+f"(c[0]), "+f"(c[1]), "+f"(c[2]), "+f"(c[3])
        : "r"(a[0]), "r"(a[1]), "r"(a[2]), "r"(a[3]), "r"(b0), "r"(b1));
}

// ---------------------------------------------------------------------------
// Prep 1: x -> fp16.  1M threads, 8 halves each.
// ---------------------------------------------------------------------------
__global__ __launch_bounds__(256) void round_xh_kernel(const float* __restrict__ x)
{
    size_t i = (size_t)blockIdx.x * 256 + threadIdx.x;
    const float4* x4 = (const float4*)x;
    float4 v0 = x4[2 * i], v1 = x4[2 * i + 1];
    uint4 u;
    u.x = f2h2(v0.x, v0.y); u.y = f2h2(v0.z, v0.w);
    u.z = f2h2(v1.x, v1.y); u.w = f2h2(v1.z, v1.w);
    ((uint4*)g_xh)[i] = u;
}

// ---------------------------------------------------------------------------
// Prep 2: transpose + round weights.  g_Wth[z][n][k] = fp16(W[z][k][n])
// ---------------------------------------------------------------------------
__global__ __launch_bounds__(256) void transpose_wh_kernel(
    const float* __restrict__ W0, const float* __restrict__ W1,
    const float* __restrict__ W2, const float* __restrict__ W3)
{
    __shared__ __half t[32][33];
    const int z = blockIdx.z;
    const float* W = (z == 0) ? W0 : (z == 1) ? W1 : (z == 2) ? W2 : W3;
    __half* out = g_Wth + (size_t)z * EMB_ * EMB_;
    const int x0 = blockIdx.x * 32, y0 = blockIdx.y * 32;   // x0: n, y0: k
    const int tx = threadIdx.x & 31, ty = threadIdx.x >> 5;
#pragma unroll
    for (int i = 0; i < 4; i++)
        t[tx][ty + i * 8] = __float2half_rn(W[(size_t)(y0 + ty + i * 8) * EMB_ + x0 + tx]);
    __syncthreads();
#pragma unroll
    for (int i = 0; i < 4; i++)
        out[(size_t)(x0 + ty + i * 8) * EMB_ + y0 + tx] = t[ty + i * 8][tx];
}

// ---------------------------------------------------------------------------
// fp16 mma.sync GEMM: out[m,n] = sum_k A[m,k]*Bt[n,k] + bias
// CTA 128x128, BK=64 (16 chunks), 256 thr = 8 warps (4m x 2n), warp 32x64.
// A and Bt fp16 [row][k]; smem rows 32 u32 data + 8 pad (stride 40),
// k pair-interleaved per 8-u32 group -> conflict-free LDS.64 fragments.
// mode: 0 = fp32 row-major out (oproj)
//       1 = fp16 scatter [bh][s][d] (K)
//       2 = fp16 scatter * 0.125   (Q)
//       3 = fp16 [bh][d][s] out; rows are emb, cols are m (V^T swapped GEMM;
//           bias indexed by ROW)
// ---------------------------------------------------------------------------
__device__ __forceinline__ void gemm_h_body(
    const __half* __restrict__ A, const __half* __restrict__ Bt,
    const float* __restrict__ bias, void* __restrict__ outv, int mode)
{
    __shared__ uint32_t As[128 * 40];
    __shared__ uint32_t Bs[128 * 40];

    const int tid  = threadIdx.x;
    const int lane = tid & 31;
    const int wid  = tid >> 5;
    const int wm   = wid & 3;
    const int wn   = wid >> 2;
    const int m0   = blockIdx.y * 128;
    const int n0   = blockIdx.x * 128;
    const int gm   = wm * 32;
    const int gn   = wn * 64;
    const int row4 = lane >> 2;
    const int kq   = lane & 3;

    float acc[2][8][4];
#pragma unroll
    for (int mt = 0; mt < 2; mt++)
#pragma unroll
        for (int nt = 0; nt < 8; nt++)
#pragma unroll
            for (int i = 0; i < 4; i++) acc[mt][nt][i] = 0.f;

    // loader: 512 (row, seg16k) slots per matrix, 2 per thread
    const __half* asrc[2];
    const __half* bsrc[2];
    uint32_t* sA[2];
    uint32_t* sB[2];
#pragma unroll
    for (int i = 0; i < 2; i++) {
        int v   = tid + 256 * i;
        int row = v >> 2;
        int seg = v & 3;
        asrc[i] = A  + (size_t)(m0 + row) * EMB_ + seg * 16;
        bsrc[i] = Bt + (size_t)(n0 + row) * EMB_ + seg * 16;
        sA[i] = &As[row * 40 + seg * 8];
        sB[i] = &Bs[row * 40 + seg * 8];
    }

    uint4 pa[2][2], pb[2][2];
#pragma unroll
    for (int i = 0; i < 2; i++) {
        pa[i][0] = *(const uint4*)(asrc[i]);
        pa[i][1] = *(const uint4*)(asrc[i] + 8);
        pb[i][0] = *(const uint4*)(bsrc[i]);
        pb[i][1] = *(const uint4*)(bsrc[i] + 8);
    }

#pragma unroll 1
    for (int c = 0; c < 16; c++) {
        if (c > 0) __syncthreads();
#pragma unroll
        for (int i = 0; i < 2; i++) {
            uint4 l0 = pa[i][0], l1 = pa[i][1];
            uint4 u0, u1;
            u0.x = l0.x; u0.y = l1.x; u0.z = l0.y; u0.w = l1.y;
            u1.x = l0.z; u1.y = l1.z; u1.z = l0.w; u1.w = l1.w;
            *(uint4*)sA[i] = u0;
            *(uint4*)(sA[i] + 4) = u1;
            l0 = pb[i][0]; l1 = pb[i][1];
            u0.x = l0.x; u0.y = l1.x; u0.z = l0.y; u0.w = l1.y;
            u1.x = l0.z; u1.y = l1.z; u1.z = l0.w; u1.w = l1.w;
            *(uint4*)sB[i] = u0;
            *(uint4*)(sB[i] + 4) = u1;
        }
        __syncthreads();

        if (c < 15) {
            size_t ka = (size_t)(c + 1) * 64;   // halves
#pragma unroll
            for (int i = 0; i < 2; i++) {
                pa[i][0] = *(const uint4*)(asrc[i] + ka);
                pa[i][1] = *(const uint4*)(asrc[i] + ka + 8);
                pb[i][0] = *(const uint4*)(bsrc[i] + ka);
                pb[i][1] = *(const uint4*)(bsrc[i] + ka + 8);
            }
        }

#pragma unroll
        for (int s = 0; s < 4; s++) {
            const int sc = s * 8 + 2 * kq;
            uint32_t a[2][4];
#pragma unroll
            for (int mt = 0; mt < 2; mt++) {
                uint2 qa = *(uint2*)&As[(gm + mt * 16 + row4) * 40 + sc];
                uint2 qb = *(uint2*)&As[(gm + mt * 16 + row4 + 8) * 40 + sc];
                a[mt][0] = qa.x; a[mt][1] = qb.x;
                a[mt][2] = qa.y; a[mt][3] = qb.y;
            }
#pragma unroll
            for (int nt = 0; nt < 8; nt++) {
                uint2 kb = *(uint2*)&Bs[(gn + nt * 8 + row4) * 40 + sc];
                mma_f16(acc[0][nt], a[0], kb.x, kb.y);
                mma_f16(acc[1][nt], a[1], kb.x, kb.y);
            }
        }
    }

    // epilogue
#pragma unroll
    for (int mt = 0; mt < 2; mt++) {
        int r0 = m0 + gm + mt * 16 + row4;
#pragma unroll
        for (int nt = 0; nt < 8; nt++) {
            int cc = n0 + gn + nt * 8 + 2 * kq;
            if (mode == 3) {
                // rows = emb (n of V), cols = m.  bias by row.
                float bv0 = bias[r0], bv1 = bias[r0 + 8];
                uint32_t h0 = f2h2(acc[mt][nt][0] + bv0, acc[mt][nt][1] + bv0);
                uint32_t h1 = f2h2(acc[mt][nt][2] + bv1, acc[mt][nt][3] + bv1);
                __half* out = (__half*)outv;
                int b = cc >> 11, sq = cc & 2047;
                int h = r0 >> 6, d0 = r0 & 63;
                int hB = (r0 + 8) >> 6, dB = (r0 + 8) & 63;
                *(uint32_t*)(out + (((size_t)(b * H_ + h) * DH_ + d0) * S_ + sq)) = h0;
                *(uint32_t*)(out + (((size_t)(b * H_ + hB) * DH_ + dB) * S_ + sq)) = h1;
            } else if (mode == 0) {
                float* out = (float*)outv;
                float2 v0, v1;
                v0.x = acc[mt][nt][0] + bias[cc];
                v0.y = acc[mt][nt][1] + bias[cc + 1];
                v1.x = acc[mt][nt][2] + bias[cc];
                v1.y = acc[mt][nt][3] + bias[cc + 1];
                *(float2*)(out + (size_t)r0 * EMB_ + cc) = v0;
                *(float2*)(out + (size_t)(r0 + 8) * EMB_ + cc) = v1;
            } else {
                float s0 = acc[mt][nt][0] + bias[cc];
                float s1 = acc[mt][nt][1] + bias[cc + 1];
                float s2 = acc[mt][nt][2] + bias[cc];
                float s3 = acc[mt][nt][3] + bias[cc + 1];
                if (mode == 2) { s0 *= 0.125f; s1 *= 0.125f; s2 *= 0.125f; s3 *= 0.125f; }
                __half* out = (__half*)outv;
                int h = cc >> 6, d = cc & 63;
                int b0r = r0 >> 11, sq0 = r0 & 2047;
                int b1r = (r0 + 8) >> 11, sq1 = (r0 + 8) & 2047;
                *(uint32_t*)(out + (((size_t)(b0r * H_ + h) * S_ + sq0) * DH_ + d)) = f2h2(s0, s1);
                *(uint32_t*)(out + (((size_t)(b1r * H_ + h) * S_ + sq1) * DH_ + d)) = f2h2(s2, s3);
            }
        }
    }
}

__global__ __launch_bounds__(256, 2) void qk_mma_kernel(
    const float* __restrict__ bq, const float* __restrict__ bk)
{
    const int z = blockIdx.z;            // 0 = Q, 1 = K
    const __half* Bt = g_Wth + (size_t)z * (EMB_ * EMB_);
    gemm_h_body(g_xh, Bt, z ? bk : bq, z ? (void*)g_Kh : (void*)g_Qh, z ? 1 : 2);
}

__global__ __launch_bounds__(256, 2) void vT_mma_kernel(const float* __restrict__ bv)
{
    // swapped GEMM: A = Wv^T [n][k], Bt = x [m][k]  -> out = V^T
    gemm_h_body(g_Wth + (size_t)2 * (EMB_ * EMB_), g_xh, bv, (void*)g_Vth, 3);
}

__global__ __launch_bounds__(256, 2) void oproj_mma_kernel(
    const float* __restrict__ bo, float* __restrict__ out)
{
    gemm_h_body(g_ctxh, g_Wth + (size_t)3 * (EMB_ * EMB_), bo, out, 0);
}

// ---------------------------------------------------------------------------
// Flash attention fp16 v5: P lives in registers (fp16 A-frag = direct pack of
// softmax'd accumulator — no smem, no shuffles).  64-query CTA, 2 CTAs/SM.
// 8 warps: wm (16 q rows each) x wn (64-key half); partial O merged at end.
// Smem (u32): QS[64][40] @0, KS[128][40] @2560, VT[64][72] @7680,
//             RED[128] @12288, LB[64] @12416  -> 12480 u32 = 49.9 KB
// ---------------------------------------------------------------------------
#define O_QS  0
#define O_KS  2560
#define O_VT  7680
#define O_RED 12288
#define O_LB  12416
#define ATTN_SMEM_U32 12480
#define ATTN_SMEM_BYTES (ATTN_SMEM_U32 * 4)

__global__ __launch_bounds__(256, 2) void attn_mma_kernel()
{
    extern __shared__ uint32_t sm[];
    float* smf = (float*)sm;

    const int tid  = threadIdx.x;
    const int lane = tid & 31;
    const int wid  = tid >> 5;
    const int wm   = wid & 3;
    const int wn   = wid >> 2;
    const int row4 = lane >> 2;
    const int kq   = lane & 3;
    const int gm   = wm * 16;
    const int gn   = wn * 64;

    const int bh = blockIdx.y;
    const int q0 = blockIdx.x * 64;

    const __half* Qg = g_Qh + ((size_t)bh * S_ + q0) * DH_;
    const __half* Kg = g_Kh + (size_t)bh * S_ * DH_;
    const __half* Vg = g_Vth + (size_t)bh * DH_ * S_;   // [d][s]

    // ---- Q tile: 64 rows x 4 segs, pair-interleaved ----
    {
        int row = tid >> 2, seg = tid & 3;
        const uint4* p = (const uint4*)(Qg + row * DH_ + seg * 16);
        uint4 l0 = p[0], l1 = p[1];
        uint4 u0, u1;
        u0.x = l0.x; u0.y = l1.x; u0.z = l0.y; u0.w = l1.y;
        u1.x = l0.z; u1.y = l1.z; u1.z = l0.w; u1.w = l1.w;
        *(uint4*)&sm[O_QS + row * 40 + seg * 8]     = u0;
        *(uint4*)&sm[O_QS + row * 40 + seg * 8 + 4] = u1;
    }

    float Oa[8][4];
#pragma unroll
    for (int nt = 0; nt < 8; nt++)
#pragma unroll
        for (int i = 0; i < 4; i++) Oa[nt][i] = 0.f;
    float m_run[2] = {-1e30f, -1e30f};
    float l_run[2] = {0.f, 0.f};

#pragma unroll 1
    for (int kt = 0; kt < S_ / 128; kt++) {
        __syncthreads();
        const int k0 = kt * 128;
        // K: 128 rows x 4 segs (2 iters)
#pragma unroll
        for (int i = 0; i < 2; i++) {
            int v = tid + 256 * i;
            int row = v >> 2, seg = v & 3;
            const uint4* p = (const uint4*)(Kg + (size_t)(k0 + row) * DH_ + seg * 16);
            uint4 l0 = p[0], l1 = p[1];
            uint4 u0, u1;
            u0.x = l0.x; u0.y = l1.x; u0.z = l0.y; u0.w = l1.y;
            u1.x = l0.z; u1.y = l1.z; u1.z = l0.w; u1.w = l1.w;
            *(uint4*)&sm[O_KS + row * 40 + seg * 8]     = u0;
            *(uint4*)&sm[O_KS + row * 40 + seg * 8 + 4] = u1;
        }
        // V^T: 64 d-rows x 8 key-segs (2 iters)
#pragma unroll
        for (int i = 0; i < 2; i++) {
            int v = tid + 256 * i;
            int row = v >> 3, seg = v & 7;
            const uint4* p = (const uint4*)(Vg + (size_t)row * S_ + k0 + seg * 16);
            uint4 l0 = p[0], l1 = p[1];
            uint4 u0, u1;
            u0.x = l0.x; u0.y = l1.x; u0.z = l0.y; u0.w = l1.y;
            u1.x = l0.z; u1.y = l1.z; u1.z = l0.w; u1.w = l1.w;
            *(uint4*)&sm[O_VT + row * 72 + seg * 8]     = u0;
            *(uint4*)&sm[O_VT + row * 72 + seg * 8 + 4] = u1;
        }
        __syncthreads();

        // ---- S = Q K^T over this wn's 64 keys (4 dh-steps) ----
        float acc[8][4];
#pragma unroll
        for (int nt = 0; nt < 8; nt++)
#pragma unroll
            for (int i = 0; i < 4; i++) acc[nt][i] = 0.f;

#pragma unroll
        for (int s = 0; s < 4; s++) {
            const int sc = s * 8 + 2 * kq;
            uint2 qa = *(uint2*)&sm[O_QS + (gm + row4) * 40 + sc];
            uint2 qb = *(uint2*)&sm[O_QS + (gm + row4 + 8) * 40 + sc];
            uint32_t a[4];
            a[0] = qa.x; a[1] = qb.x; a[2] = qa.y; a[3] = qb.y;
#pragma unroll
            for (int nt = 0; nt < 8; nt++) {
                uint2 kb = *(uint2*)&sm[O_KS + (gn + nt * 8 + row4) * 40 + sc];
                mma_f16(acc[nt], a, kb.x, kb.y);
            }
        }

        // ---- online softmax (global max via smem; sums stay partial) ----
        float rmax[2];
        rmax[0] = acc[0][0];
        rmax[1] = acc[0][2];
#pragma unroll
        for (int nt = 0; nt < 8; nt++) {
            rmax[0] = fmaxf(rmax[0], fmaxf(acc[nt][0], acc[nt][1]));
            rmax[1] = fmaxf(rmax[1], fmaxf(acc[nt][2], acc[nt][3]));
        }
#pragma unroll
        for (int h = 0; h < 2; h++) {
            rmax[h] = fmaxf(rmax[h], __shfl_xor_sync(0xffffffffu, rmax[h], 1));
            rmax[h] = fmaxf(rmax[h], __shfl_xor_sync(0xffffffffu, rmax[h], 2));
        }
        if (kq == 0) {
            smf[O_RED + wn * 64 + gm + row4]     = rmax[0];
            smf[O_RED + wn * 64 + gm + 8 + row4] = rmax[1];
        }
        __syncthreads();

        float scale[2];
#pragma unroll
        for (int h = 0; h < 2; h++) {
            int r = gm + h * 8 + row4;
            float mtile = fmaxf(smf[O_RED + r], smf[O_RED + 64 + r]);
            float mnew  = fmaxf(m_run[h], mtile);
            scale[h] = __expf(m_run[h] - mnew);
            m_run[h] = mnew;
        }

#pragma unroll
        for (int nt = 0; nt < 8; nt++) {
            acc[nt][0] = __expf(acc[nt][0] - m_run[0]);
            acc[nt][1] = __expf(acc[nt][1] - m_run[0]);
            acc[nt][2] = __expf(acc[nt][2] - m_run[1]);
            acc[nt][3] = __expf(acc[nt][3] - m_run[1]);
        }
        float rsum[2] = {0.f, 0.f};
#pragma unroll
        for (int nt = 0; nt < 8; nt++) {
            rsum[0] += acc[nt][0] + acc[nt][1];
            rsum[1] += acc[nt][2] + acc[nt][3];
        }
#pragma unroll
        for (int h = 0; h < 2; h++) {
            rsum[h] += __shfl_xor_sync(0xffffffffu, rsum[h], 1);
            rsum[h] += __shfl_xor_sync(0xffffffffu, rsum[h], 2);
            l_run[h] = l_run[h] * scale[h] + rsum[h];
        }

        // rescale partial O
#pragma unroll
        for (int nt = 0; nt < 8; nt++) {
            Oa[nt][0] *= scale[0];
            Oa[nt][1] *= scale[0];
            Oa[nt][2] *= scale[1];
            Oa[nt][3] *= scale[1];
        }

        // ---- O += P V: P packed fp16 straight from acc ----
#pragma unroll
        for (int ks = 0; ks < 4; ks++) {
            uint32_t ap[4];
            ap[0] = f2h2(acc[2 * ks][0],     acc[2 * ks][1]);
            ap[1] = f2h2(acc[2 * ks][2],     acc[2 * ks][3]);
            ap[2] = f2h2(acc[2 * ks + 1][0], acc[2 * ks + 1][1]);
            ap[3] = f2h2(acc[2 * ks + 1][2], acc[2 * ks + 1][3]);
            const int vcol = (wn * 4 + ks) * 8 + 2 * kq;
#pragma unroll
            for (int nt = 0; nt < 8; nt++) {
                uint2 vb = *(uint2*)&sm[O_VT + (nt * 8 + row4) * 72 + vcol];
                mma_f16(Oa[nt], ap, vb.x, vb.y);
            }
        }
    }

    // ---- merge wn partials, normalize, write ctx fp16 ----
    __syncthreads();   // PV reads of VT/KS done; reuse KS as Obuf
    if (wn == 1) {
#pragma unroll
        for (int nt = 0; nt < 8; nt++) {
            int d = nt * 8 + 2 * kq;
            float2 v0, v1;
            v0.x = Oa[nt][0]; v0.y = Oa[nt][1];
            v1.x = Oa[nt][2]; v1.y = Oa[nt][3];
            *(float2*)&smf[O_KS + (gm + row4) * 72 + d]     = v0;
            *(float2*)&smf[O_KS + (gm + 8 + row4) * 72 + d] = v1;
        }
        if (kq == 0) {
            smf[O_LB + gm + row4]     = l_run[0];
            smf[O_LB + gm + 8 + row4] = l_run[1];
        }
    }
    __syncthreads();
    if (wn == 0) {
        const int b = bh >> 4;
        const int h = bh & 15;
        int r0 = gm + row4;
        int r1 = gm + 8 + row4;
        float inv0 = 1.f / (l_run[0] + smf[O_LB + r0]);
        float inv1 = 1.f / (l_run[1] + smf[O_LB + r1]);
        __half* o0 = g_ctxh + ((size_t)(b * S_) + q0 + r0) * EMB_ + h * DH_;
        __half* o1 = g_ctxh + ((size_t)(b * S_) + q0 + r1) * EMB_ + h * DH_;
#pragma unroll
        for (int nt = 0; nt < 8; nt++) {
            int d = nt * 8 + 2 * kq;
            float2 p0 = *(float2*)&smf[O_KS + r0 * 72 + d];
            float2 p1 = *(float2*)&smf[O_KS + r1 * 72 + d];
            *(uint32_t*)(o0 + d) = f2h2((Oa[nt][0] + p0.x) * inv0,
                                        (Oa[nt][1] + p0.y) * inv0);
            *(uint32_t*)(o1 + d) = f2h2((Oa[nt][2] + p1.x) * inv1,
                                        (Oa[nt][3] + p1.y) * inv1);
        }
    }
}

// ---------------------------------------------------------------------------
// Launch
// ---------------------------------------------------------------------------
extern "C" void kernel_launch(void* const* d_in, const int* in_sizes, int n_in,
                              void* d_out, int out_size)
{
    const float* x  = (const float*)d_in[0];
    const float* Wq = (const float*)d_in[1];
    const float* bq = (const float*)d_in[2];
    const float* Wk = (const float*)d_in[3];
    const float* bk = (const float*)d_in[4];
    const float* Wv = (const float*)d_in[5];
    const float* bv = (const float*)d_in[6];
    const float* Wo = (const float*)d_in[7];
    const float* bo = (const float*)d_in[8];
    float* out = (float*)d_out;

    cudaFuncSetAttribute(attn_mma_kernel,
                         cudaFuncAttributeMaxDynamicSharedMemorySize, ATTN_SMEM_BYTES);

    round_xh_kernel<<<4096, 256>>>(x);                    // 1M threads x 8 halves

    dim3 gT(EMB_ / 32, EMB_ / 32, 4);                     // (32, 32, 4)
    transpose_wh_kernel<<<gT, 256>>>(Wq, Wk, Wv, Wo);

    dim3 gQK(EMB_ / 128, M_ / 128, 2);                    // (8, 64, 2)
    qk_mma_kernel<<<gQK, 256>>>(bq, bk);

    dim3 gV(M_ / 128, EMB_ / 128);                        // (64, 8) swapped
    vT_mma_kernel<<<gV, 256>>>(bv);

    dim3 gAttn(S_ / 64, B_ * H_);                         // (32, 64)
    attn_mma_kernel<<<gAttn, 256, ATTN_SMEM_BYTES>>>();

    dim3 gO(EMB_ / 128, M_ / 128);                        // (8, 64)
    oproj_mma_kernel<<<gO, 256>>>(bo, out);
}